// round 15
// baseline (speedup 1.0000x reference)
#include <cuda_runtime.h>
#include <cstdint>
#include <math.h>
#include <float.h>
#include <cub/cub.cuh>

#define NPTS     4096
#define MAXQ     32768            // B=8 * 4096
#define NRUNS    2
#define RUNP     (NPTS / NRUNS)   // 2048
#define SORT_THR 1024
#define SORT_IPT (RUNP / SORT_THR) // 2
#define NN_THR   256
#define WPB      (NN_THR / 32)

typedef unsigned long long ull;

// Sorted points: per (set, batch, run) a z-ascending run of RUNP float4
// {x, y, z, orig_idx_bits}. Rewritten fully each launch (replay-safe).
__device__ float4 g_pts[2][MAXQ];

// Order-preserving float <-> uint32 (total order incl. negatives).
__device__ __forceinline__ unsigned int fkey(float f) {
    unsigned int b = __float_as_uint(f);
    return (b & 0x80000000u) ? ~b : (b | 0x80000000u);
}
__device__ __forceinline__ float inv_fkey(unsigned int k) {
    unsigned int b = (k & 0x80000000u) ? (k & 0x7FFFFFFFu) : ~k;
    return __uint_as_float(b);
}

// Radix-sort one run (2048 points) of one (batch, set) by z.
__global__ void __launch_bounds__(SORT_THR) sort_kernel(
    const float* __restrict__ X1, const float* __restrict__ X2, float* out)
{
    typedef cub::BlockRadixSort<unsigned int, SORT_THR, SORT_IPT,
                                unsigned int> BRS;
    __shared__ typename BRS::TempStorage ts;

    const int b   = blockIdx.x;                // batch
    const int s   = blockIdx.y;                // set
    const int run = blockIdx.z;                // run within set
    const int tid = threadIdx.x;
    const float* __restrict__ P = (s ? X2 : X1) + (size_t)b * NPTS * 6;

    if (b == 0 && s == 0 && run == 0 && tid == 0) out[0] = 0.0f;

    unsigned int k[SORT_IPT], v[SORT_IPT];
#pragma unroll
    for (int i = 0; i < SORT_IPT; i++) {
        int e = run * RUNP + tid * SORT_IPT + i;   // original index
        k[i] = fkey(P[(size_t)e * 6 + 2]);
        v[i] = (unsigned int)e;
    }
    BRS(ts).Sort(k, v);

#pragma unroll
    for (int i = 0; i < SORT_IPT; i++) {
        int r = tid * SORT_IPT + i;
        int idx = (int)v[i];
        float2 xy = *(const float2*)(P + (size_t)idx * 6);
        g_pts[s][b * NPTS + run * RUNP + r] =
            make_float4(xy.x, xy.y, inv_fkey(k[i]), __int_as_float(idx));
    }
}

__device__ __forceinline__ float normal_diff2(const float* __restrict__ a,
                                              const float* __restrict__ b) {
    float ax = a[0], ay = a[1], az = a[2];
    float bx = b[0], by = b[1], bz = b[2];
    float ia = 1.0f / fmaxf(sqrtf(fmaf(ax, ax, fmaf(ay, ay, az * az))), 1e-12f);
    float ib = 1.0f / fmaxf(sqrtf(fmaf(bx, bx, fmaf(by, by, bz * bz))), 1e-12f);
    float dx = ax * ia - bx * ib;
    float dy = ay * ia - by * ib;
    float dz = az * ia - bz * ib;
    return fmaf(dx, dx, fmaf(dy, dy, dz * dz));
}

// NN + reduce: ONE WARP per query, 4 fronts of 8 lanes (run0-right,
// run0-left, run1-right, run1-left), 32 candidates per step. Right fronts
// walk +8/step (z ascending), left fronts walk -8/step (z descending).
// Pruning threshold t is FROZEN except two tightenings (steps 0 and 3),
// so the stop test has no warp-reduce in the loop-carried chain. Exact:
// t >= final best always, so a front stops only when all its remaining
// candidates have d >= dz^2 >= t >= best. Final per-lane (d, orig idx)
// merged via packed u64 min (ties -> smallest original index).
__global__ void __launch_bounds__(NN_THR) nn_kernel(
    const float* __restrict__ X1, const float* __restrict__ X2,
    float* __restrict__ out, float inv_nq)
{
    const int dir   = blockIdx.y;
    const int w     = blockIdx.x * WPB + (threadIdx.x >> 5);
    const int lane  = threadIdx.x & 31;
    const int batch = w / NPTS;
    const int rank  = w - batch * NPTS;

    const float4 q = g_pts[dir][w];
    const float qx = q.x, qy = q.y, qz = q.z;
    const float4* __restrict__ cb = &g_pts[dir ^ 1][(size_t)batch * NPTS];

    const int  front  = lane >> 3;             // 0..3
    const int  run    = front >> 1;
    const bool rightf = (front & 1) == 0;
    const int  fl     = lane & 7;
    const float sgn   = rightf ? 1.0f : -1.0f;
    const int   stepd = rightf ? 8 : -8;       // per-step position delta
    const float4* __restrict__ rb = cb + run * RUNP;

    const int s0 = rank >> 1;                  // expected rank within a run
    int pos = rightf ? (s0 + fl) : (s0 - 1 - fl);

    unsigned int lbest = 0xFFFFFFFFu;
    int          lidx  = 0;
    unsigned int amask = 0xFu;                 // active fronts
    float t = FLT_MAX;
    int   step = 0;

    while (amask) {
        bool act = (amask >> front) & 1u;
        bool inb = act && (pos >= 0) && (pos < RUNP);
        float4 c = inb ? rb[pos] : make_float4(0.f, 0.f, 0.f, 0.f);

        float dx = c.x - qx, dy = c.y - qy, dz = c.z - qz;
        float d  = fmaf(dx, dx, fmaf(dy, dy, dz * dz));
        unsigned int db = inb ? __float_as_uint(d) : 0xFFFFFFFFu;
        if (db < lbest) { lbest = db; lidx = __float_as_int(c.w); }

        float dzb = dz * sgn;
        bool stop = !inb || (dzb > 0.0f && dzb * dzb >= t);
        unsigned int bal = __ballot_sync(0xFFFFFFFFu, stop);
        unsigned int stopped = ((bal >> 7) & 1u) | ((bal >> 14) & 2u)
                             | ((bal >> 21) & 4u) | ((bal >> 28) & 8u);
        amask &= ~stopped;
        pos += stepd;

        if (step < 4) {                        // two threshold tightenings
            if (step == 0 || step == 3) {
                unsigned int wmin;
                asm("redux.sync.min.u32 %0, %1, 0xffffffff;"
                    : "=r"(wmin) : "r"(lbest));
                t = __uint_as_float(wmin);
            }
            step++;
        }
    }

    // Merge per-lane results: u64 min of (d_bits << 32 | orig_idx).
    ull pk = ((ull)lbest << 32) | (unsigned int)lidx;
#pragma unroll
    for (int m = 16; m >= 1; m >>= 1) {
        ull o = __shfl_xor_sync(0xFFFFFFFFu, pk, m);
        pk = o < pk ? o : pk;
    }

    float acc = 0.0f;
    if (lane == 0) {
        float dbest = __uint_as_float((unsigned int)(pk >> 32));
        int   cidx  = (int)(pk & 0xFFFFFFFFull);
        int   qidx  = __float_as_int(q.w);
        const float* Qn = (dir ? X2 : X1)
                        + (size_t)(batch * NPTS + qidx) * 6 + 3;
        const float* Cn = (dir ? X1 : X2)
                        + (size_t)(batch * NPTS + cidx) * 6 + 3;
        acc = dbest + normal_diff2(Qn, Cn);
    }

    __shared__ float ssum[WPB];
    if (lane == 0) ssum[threadIdx.x >> 5] = acc;
    __syncthreads();
    if (threadIdx.x < 32) {
        float v = (lane < WPB) ? ssum[lane] : 0.0f;
#pragma unroll
        for (int o = WPB / 2; o >= 1; o >>= 1)
            v += __shfl_down_sync(0xFFFFFFFFu, v, o);
        if (lane == 0) atomicAdd(out, v * inv_nq);
    }
}

extern "C" void kernel_launch(void* const* d_in, const int* in_sizes, int n_in,
                              void* d_out, int out_size)
{
    const float* x1 = (const float*)d_in[0];
    const float* x2 = (const float*)d_in[1];
    float* out = (float*)d_out;

    int total = in_sizes[0];
    int B  = total / (NPTS * 6);      // 8
    int nq = B * NPTS;                // 32768

    dim3 sgrid(B, 2, NRUNS);          // (8, 2, 2) = 32 CTAs
    sort_kernel<<<sgrid, SORT_THR>>>(x1, x2, out);

    dim3 ngrid(nq / WPB, 2);          // (4096, 2), warp per query
    nn_kernel<<<ngrid, NN_THR>>>(x1, x2, out, 1.0f / (float)nq);
}

// round 16
// speedup vs baseline: 3.7398x; 3.7398x over previous
#include <cuda_runtime.h>
#include <cstdint>
#include <math.h>
#include <float.h>
#include <cub/cub.cuh>

#define NPTS     4096
#define MAXQ     32768             // B=8 * 4096
#define NRUNS    2
#define RUNP     (NPTS / NRUNS)    // 2048
#define SORT_THR 1024
#define SORT_IPT (RUNP / SORT_THR) // 2
#define NN_THR   256
#define WPB      (NN_THR / 32)

typedef unsigned long long ull;

// Sorted points: per (set, batch, run) a z-ascending run of RUNP float4
// {x, y, z, orig_idx_bits}. Rewritten fully each launch (replay-safe).
__device__ float4 g_pts[2][MAXQ];

// Order-preserving float <-> uint32 (total order incl. negatives).
__device__ __forceinline__ unsigned int fkey(float f) {
    unsigned int b = __float_as_uint(f);
    return (b & 0x80000000u) ? ~b : (b | 0x80000000u);
}
__device__ __forceinline__ float inv_fkey(unsigned int k) {
    unsigned int b = (k & 0x80000000u) ? (k & 0x7FFFFFFFu) : ~k;
    return __uint_as_float(b);
}

// Radix-sort one run (2048 points) of one (batch, set) by z.
__global__ void __launch_bounds__(SORT_THR) sort_kernel(
    const float* __restrict__ X1, const float* __restrict__ X2, float* out)
{
    typedef cub::BlockRadixSort<unsigned int, SORT_THR, SORT_IPT,
                                unsigned int> BRS;
    __shared__ typename BRS::TempStorage ts;

    const int b   = blockIdx.x;                // batch
    const int s   = blockIdx.y;                // set
    const int run = blockIdx.z;                // run within set
    const int tid = threadIdx.x;
    const float* __restrict__ P = (s ? X2 : X1) + (size_t)b * NPTS * 6;

    if (b == 0 && s == 0 && run == 0 && tid == 0) out[0] = 0.0f;

    unsigned int k[SORT_IPT], v[SORT_IPT];
#pragma unroll
    for (int i = 0; i < SORT_IPT; i++) {
        int e = run * RUNP + tid * SORT_IPT + i;   // original index
        k[i] = fkey(P[(size_t)e * 6 + 2]);
        v[i] = (unsigned int)e;
    }
    BRS(ts).Sort(k, v);

#pragma unroll
    for (int i = 0; i < SORT_IPT; i++) {
        int r = tid * SORT_IPT + i;
        int idx = (int)v[i];
        float2 xy = *(const float2*)(P + (size_t)idx * 6);
        g_pts[s][b * NPTS + run * RUNP + r] =
            make_float4(xy.x, xy.y, inv_fkey(k[i]), __int_as_float(idx));
    }
}

__device__ __forceinline__ float normal_diff2(const float* __restrict__ a,
                                              const float* __restrict__ b) {
    float ax = a[0], ay = a[1], az = a[2];
    float bx = b[0], by = b[1], bz = b[2];
    float ia = 1.0f / fmaxf(sqrtf(fmaf(ax, ax, fmaf(ay, ay, az * az))), 1e-12f);
    float ib = 1.0f / fmaxf(sqrtf(fmaf(bx, bx, fmaf(by, by, bz * bz))), 1e-12f);
    float dx = ax * ia - bx * ib;
    float dy = ay * ia - by * ib;
    float dz = az * ia - bz * ib;
    return fmaf(dx, dx, fmaf(dy, dy, dz * dz));
}

// NN + reduce: one WARP = 32 consecutive sorted queries of one run (lane <->
// query). Candidates scanned in tiles of 32 per run: coalesced LDG -> smem
// stage -> broadcast LDS; each lane tracks min e = |c|^2 - 2<q,c> for ITS
// query (argmin(e) == argmin(d)). Right tiles ascend from the query group's
// own-run rank; left tiles descend. Exact stop: lane done when the tile's
// boundary z (max for right / min for left; monotone beyond the tile)
// satisfies dz > 0 && dz^2 >= e + |q|^2 = current best d; warp stops a
// direction when ALL lanes are done. Right covers [rq0, RUNP), left covers
// [0, rq0) -> full coverage, no approximation.
__global__ void __launch_bounds__(NN_THR) nn_kernel(
    const float* __restrict__ X1, const float* __restrict__ X2,
    float* __restrict__ out, float inv_nq)
{
    __shared__ float4 sc[WPB][32];
    __shared__ int    si[WPB][32];

    const int dir   = blockIdx.y;
    const int wid   = threadIdx.x >> 5;
    const int lane  = threadIdx.x & 31;
    const int wq    = blockIdx.x * WPB + wid;      // warp index within dir
    const int qslot = wq * 32;                     // 0..MAXQ-1, 32-aligned
    const int batch = qslot / NPTS;
    const int qoff  = qslot - batch * NPTS;        // within batch (runs concat)
    const int rq0   = qoff & (RUNP - 1);           // rank of lane 0 in own run

    const float4 q = g_pts[dir][batch * NPTS + qoff + lane];
    const float qx = q.x, qy = q.y, qz = q.z;
    const float nx = -2.0f * qx, ny = -2.0f * qy, nz = -2.0f * qz;
    const float sq = fmaf(qx, qx, fmaf(qy, qy, qz * qz));
    const int qidx = __float_as_int(q.w);

    float beste = FLT_MAX;
    int   bidx  = 0;

    const float4* __restrict__ cbase = &g_pts[dir ^ 1][(size_t)batch * NPTS];

#pragma unroll 1
    for (int crun = 0; crun < NRUNS; crun++) {
        const float4* __restrict__ rb = cbase + crun * RUNP;

        // ---- right scan: covers [rq0, RUNP) ----
#pragma unroll 1
        for (int pb = rq0; pb < RUNP; pb += 32) {
            int p = pb + lane;
            float4 c = (p < RUNP) ? rb[p]
                                  : make_float4(0.f, 0.f, 3.0e37f, 0.f);
            float cw = fmaf(c.x, c.x, fmaf(c.y, c.y, c.z * c.z)); // inf if dummy
            sc[wid][lane] = make_float4(c.x, c.y, c.z, cw);
            si[wid][lane] = __float_as_int(c.w);
            __syncwarp();
#pragma unroll 8
            for (int k = 0; k < 32; k++) {
                float4 ck = sc[wid][k];
                float e = fmaf(nx, ck.x, fmaf(ny, ck.y, fmaf(nz, ck.z, ck.w)));
                if (e < beste) { beste = e; bidx = si[wid][k]; }
            }
            float bz  = sc[wid][31].z;             // max z in tile
            float dzb = bz - qz;
            bool done = (dzb > 0.0f) && (dzb * dzb >= beste + sq);
            __syncwarp();
            if (__all_sync(0xFFFFFFFFu, done)) break;
        }

        // ---- left scan: covers [0, rq0) ----
#pragma unroll 1
        for (int pb = rq0 - 32; pb > -32; pb -= 32) {
            int p = pb + lane;
            float4 c = (p >= 0) ? rb[p]
                                : make_float4(0.f, 0.f, -3.0e37f, 0.f);
            float cw = fmaf(c.x, c.x, fmaf(c.y, c.y, c.z * c.z));
            sc[wid][lane] = make_float4(c.x, c.y, c.z, cw);
            si[wid][lane] = __float_as_int(c.w);
            __syncwarp();
#pragma unroll 8
            for (int k = 0; k < 32; k++) {
                float4 ck = sc[wid][k];
                float e = fmaf(nx, ck.x, fmaf(ny, ck.y, fmaf(nz, ck.z, ck.w)));
                if (e < beste) { beste = e; bidx = si[wid][k]; }
            }
            float bz  = sc[wid][0].z;              // min z in tile
            float dzb = qz - bz;
            bool done = (dzb > 0.0f) && (dzb * dzb >= beste + sq);
            __syncwarp();
            if (__all_sync(0xFFFFFFFFu, done)) break;
        }
    }

    // Per-lane query result: distance + normal term.
    float dbest = sq + beste;
    const float* Qn = (dir ? X2 : X1) + (size_t)(batch * NPTS + qidx) * 6 + 3;
    const float* Cn = (dir ? X1 : X2) + (size_t)(batch * NPTS + bidx) * 6 + 3;
    float acc = dbest + normal_diff2(Qn, Cn);

    // Block reduction -> one atomicAdd per block.
    __shared__ float ssum[WPB];
    float v = acc;
#pragma unroll
    for (int o = 16; o > 0; o >>= 1) v += __shfl_down_sync(0xFFFFFFFFu, v, o);
    if (lane == 0) ssum[wid] = v;
    __syncthreads();
    if (threadIdx.x < 32) {
        v = (lane < WPB) ? ssum[lane] : 0.0f;
#pragma unroll
        for (int o = WPB / 2; o >= 1; o >>= 1)
            v += __shfl_down_sync(0xFFFFFFFFu, v, o);
        if (lane == 0) atomicAdd(out, v * inv_nq);
    }
}

extern "C" void kernel_launch(void* const* d_in, const int* in_sizes, int n_in,
                              void* d_out, int out_size)
{
    const float* x1 = (const float*)d_in[0];
    const float* x2 = (const float*)d_in[1];
    float* out = (float*)d_out;

    int total = in_sizes[0];
    int B  = total / (NPTS * 6);      // 8
    int nq = B * NPTS;                // 32768

    dim3 sgrid(B, 2, NRUNS);          // (8, 2, 2) = 32 CTAs
    sort_kernel<<<sgrid, SORT_THR>>>(x1, x2, out);

    // one warp per 32 queries: (32768/32)/WPB blocks per dir
    dim3 ngrid((nq / 32) / WPB, 2);   // (128, 2) = 256 CTAs
    nn_kernel<<<ngrid, NN_THR>>>(x1, x2, out, 1.0f / (float)nq);
}

// round 17
// speedup vs baseline: 6.0024x; 1.6050x over previous
#include <cuda_runtime.h>
#include <cstdint>
#include <math.h>
#include <float.h>
#include <cub/cub.cuh>

#define NPTS     4096
#define MAXQ     32768             // B=8 * 4096
#define NRUNS    4
#define RUNP     (NPTS / NRUNS)    // 1024
#define SORT_THR 512
#define SORT_IPT (RUNP / SORT_THR) // 2
#define NN_THR   256
#define WPB      (NN_THR / 32)
#define QGRP     (MAXQ / 32)       // 1024 query groups per dir

typedef unsigned long long ull;

// Sorted points: per (set, batch, run) a z-ascending run of RUNP float4
// {x, y, z, orig_idx_bits}. Rewritten fully each launch (replay-safe).
__device__ float4 g_pts[2][MAXQ];
// Zero-initialized best per (dir, original query row): ~((fkey(e)<<32)|idx).
// atomicMax, 0 = empty sentinel; merge resets to 0 (replay-safe).
__device__ ull g_best[2][MAXQ];

__device__ __forceinline__ unsigned int fkey(float f) {
    unsigned int b = __float_as_uint(f);
    return (b & 0x80000000u) ? ~b : (b | 0x80000000u);
}
__device__ __forceinline__ float inv_fkey(unsigned int k) {
    unsigned int b = (k & 0x80000000u) ? (k & 0x7FFFFFFFu) : ~k;
    return __uint_as_float(b);
}

// Radix-sort one run (1024 points) of one (batch, set) by z.
__global__ void __launch_bounds__(SORT_THR) sort_kernel(
    const float* __restrict__ X1, const float* __restrict__ X2, float* out)
{
    typedef cub::BlockRadixSort<unsigned int, SORT_THR, SORT_IPT,
                                unsigned int> BRS;
    __shared__ typename BRS::TempStorage ts;

    const int b   = blockIdx.x;
    const int s   = blockIdx.y;
    const int run = blockIdx.z;
    const int tid = threadIdx.x;
    const float* __restrict__ P = (s ? X2 : X1) + (size_t)b * NPTS * 6;

    if (b == 0 && s == 0 && run == 0 && tid == 0) out[0] = 0.0f;

    unsigned int k[SORT_IPT], v[SORT_IPT];
#pragma unroll
    for (int i = 0; i < SORT_IPT; i++) {
        int e = run * RUNP + tid * SORT_IPT + i;
        k[i] = fkey(P[(size_t)e * 6 + 2]);
        v[i] = (unsigned int)e;
    }
    BRS(ts).Sort(k, v);

#pragma unroll
    for (int i = 0; i < SORT_IPT; i++) {
        int r = tid * SORT_IPT + i;
        int idx = (int)v[i];
        float2 xy = *(const float2*)(P + (size_t)idx * 6);
        g_pts[s][b * NPTS + run * RUNP + r] =
            make_float4(xy.x, xy.y, inv_fkey(k[i]), __int_as_float(idx));
    }
}

// NN: one WARP per (32-query group, dir, candidate-run, side). Lane <->
// query. Tiles of 32 candidates staged in smem; each lane tracks min
// e = |c|^2 - 2<q,c> for its query in 4 independent chains (short dep
// chains). Side stop (exact): lane done when the tile's boundary z
// (monotone beyond the tile) has dz > 0 && dz^2 >= min(e) + |q|^2; the
// warp stops when ALL lanes are done. Right covers [rq0, RUNP), left
// [0, rq0) -> full coverage. Per-side pruning uses the side's own best
// (>= final best, so pruning is conservative = exact).
__global__ void __launch_bounds__(NN_THR) nn_kernel()
{
    __shared__ float4 sc[WPB][32];
    __shared__ int    si[WPB][32];

    const int dir   = blockIdx.y;
    const int rs    = blockIdx.z;              // run*2 + side
    const int crun  = rs >> 1;
    const bool rightf = (rs & 1) == 0;
    const int wid   = threadIdx.x >> 5;
    const int lane  = threadIdx.x & 31;
    const int group = blockIdx.x * WPB + wid;  // 0..QGRP-1
    const int qslot = group * 32;
    const int batch = qslot / NPTS;
    const int qoff  = qslot - batch * NPTS;
    const int rq0   = qoff & (RUNP - 1);       // lane0's rank in its own run

    const float4 q = g_pts[dir][batch * NPTS + qoff + lane];
    const float qx = q.x, qy = q.y, qz = q.z;
    const float nx = -2.0f * qx, ny = -2.0f * qy, nz = -2.0f * qz;
    const float sq = fmaf(qx, qx, fmaf(qy, qy, qz * qz));
    const int qidx = __float_as_int(q.w);

    const float4* __restrict__ rb =
        &g_pts[dir ^ 1][(size_t)batch * NPTS + crun * RUNP];

    float b0 = FLT_MAX, b1 = FLT_MAX, b2 = FLT_MAX, b3 = FLT_MAX;
    int   j0 = 0, j1 = 0, j2 = 0, j3 = 0;

    const float dumz = rightf ? 1.0e19f : -1.0e19f;
    const int   pbeg = rightf ? rq0 : rq0 - 32;
    const int   pstp = rightf ? 32 : -32;

#pragma unroll 1
    for (int pb = pbeg; rightf ? (pb < RUNP) : (pb > -32); pb += pstp) {
        int p = pb + lane;
        bool inb = (p >= 0) && (p < RUNP);
        float4 c;
        float cw;
        if (inb) {
            c = rb[p];
            cw = fmaf(c.x, c.x, fmaf(c.y, c.y, c.z * c.z));
        } else {
            c = make_float4(0.f, 0.f, dumz, 0.f);
            cw = 1.0e38f;                      // e huge, never selected
        }
        sc[wid][lane] = make_float4(c.x, c.y, c.z, cw);
        si[wid][lane] = __float_as_int(c.w);
        __syncwarp();

#pragma unroll
        for (int k = 0; k < 32; k += 4) {
            float4 c0 = sc[wid][k];
            float4 c1 = sc[wid][k + 1];
            float4 c2 = sc[wid][k + 2];
            float4 c3 = sc[wid][k + 3];
            float e0 = fmaf(nx, c0.x, fmaf(ny, c0.y, fmaf(nz, c0.z, c0.w)));
            float e1 = fmaf(nx, c1.x, fmaf(ny, c1.y, fmaf(nz, c1.z, c1.w)));
            float e2 = fmaf(nx, c2.x, fmaf(ny, c2.y, fmaf(nz, c2.z, c2.w)));
            float e3 = fmaf(nx, c3.x, fmaf(ny, c3.y, fmaf(nz, c3.z, c3.w)));
            if (e0 < b0) { b0 = e0; j0 = si[wid][k]; }
            if (e1 < b1) { b1 = e1; j1 = si[wid][k + 1]; }
            if (e2 < b2) { b2 = e2; j2 = si[wid][k + 2]; }
            if (e3 < b3) { b3 = e3; j3 = si[wid][k + 3]; }
        }

        float bz  = sc[wid][rightf ? 31 : 0].z;   // boundary z (monotone on)
        float dzb = rightf ? (bz - qz) : (qz - bz);
        float bmin = fminf(fminf(b0, b1), fminf(b2, b3));
        bool done = (dzb > 0.0f) && (dzb * dzb >= bmin + sq);
        __syncwarp();
        if (__all_sync(0xFFFFFFFFu, done)) break;
    }

    // Merge 4 chains -> (beste, bidx), then global per-query merge.
    float beste = b0; int bidx = j0;
    if (b1 < beste) { beste = b1; bidx = j1; }
    if (b2 < beste) { beste = b2; bidx = j2; }
    if (b3 < beste) { beste = b3; bidx = j3; }

    if (beste < FLT_MAX) {
        ull key = ((ull)fkey(beste) << 32) | (unsigned int)bidx;
        atomicMax(&g_best[dir][batch * NPTS + qidx], ~key);
    }
}

__device__ __forceinline__ float normal_diff2(const float* __restrict__ a,
                                              const float* __restrict__ b) {
    float ax = a[0], ay = a[1], az = a[2];
    float bx = b[0], by = b[1], bz = b[2];
    float ia = 1.0f / fmaxf(sqrtf(fmaf(ax, ax, fmaf(ay, ay, az * az))), 1e-12f);
    float ib = 1.0f / fmaxf(sqrtf(fmaf(bx, bx, fmaf(by, by, bz * bz))), 1e-12f);
    float dx = ax * ia - bx * ib;
    float dy = ay * ia - by * ib;
    float dz = az * ia - bz * ib;
    return fmaf(dx, dx, fmaf(dy, dy, dz * dz));
}

// Merge: one thread per (dir, query row). Read winning (e, idx), reset the
// slot (replay determinism), compute d + normal term, block-reduce, atomic.
__global__ void __launch_bounds__(NN_THR) merge_kernel(
    const float* __restrict__ X1, const float* __restrict__ X2,
    float* __restrict__ out, int nq, float inv_nq)
{
    const int gi   = blockIdx.x * NN_THR + threadIdx.x;  // 0..2*nq-1
    const int dir  = gi >= nq;
    const int q    = dir ? gi - nq : gi;
    const int batch = q / NPTS;

    ull key = ~g_best[dir][q];
    g_best[dir][q] = 0ull;                     // reset for next replay
    float e   = inv_fkey((unsigned int)(key >> 32));
    int   cidx = (int)(key & 0xFFFFFFFFull);

    const float* __restrict__ Qraw = dir ? X2 : X1;
    const float* __restrict__ Craw = dir ? X1 : X2;
    const float* p = Qraw + (size_t)q * 6;
    float sq = fmaf(p[0], p[0], fmaf(p[1], p[1], p[2] * p[2]));
    const float* cn = Craw + (size_t)(batch * NPTS + cidx) * 6 + 3;
    float acc = (sq + e) + normal_diff2(p + 3, cn);

    __shared__ float ssum[NN_THR / 32];
    float v = acc;
#pragma unroll
    for (int o = 16; o > 0; o >>= 1) v += __shfl_down_sync(0xFFFFFFFFu, v, o);
    int lane = threadIdx.x & 31, warp = threadIdx.x >> 5;
    if (lane == 0) ssum[warp] = v;
    __syncthreads();
    if (warp == 0) {
        v = (lane < NN_THR / 32) ? ssum[lane] : 0.0f;
#pragma unroll
        for (int o = 4; o > 0; o >>= 1) v += __shfl_down_sync(0xFFFFFFFFu, v, o);
        if (lane == 0) atomicAdd(out, v * inv_nq);
    }
}

extern "C" void kernel_launch(void* const* d_in, const int* in_sizes, int n_in,
                              void* d_out, int out_size)
{
    const float* x1 = (const float*)d_in[0];
    const float* x2 = (const float*)d_in[1];
    float* out = (float*)d_out;

    int total = in_sizes[0];
    int B  = total / (NPTS * 6);      // 8
    int nq = B * NPTS;                // 32768

    dim3 sgrid(B, 2, NRUNS);          // (8, 2, 4) = 64 CTAs
    sort_kernel<<<sgrid, SORT_THR>>>(x1, x2, out);

    dim3 ngrid(QGRP / WPB, 2, NRUNS * 2);   // (128, 2, 8) = 2048 CTAs
    nn_kernel<<<ngrid, NN_THR>>>();

    merge_kernel<<<2 * nq / NN_THR, NN_THR>>>(x1, x2, out, nq,
                                              1.0f / (float)nq);
}